// round 15
// baseline (speedup 1.0000x reference)
#include <cuda_runtime.h>
#include <cstddef>

// STFT via four-step FFT (1024 = 32x32), real-pair packed, 2 lanes per 32-pt FFT.
// Round-15: (a) stage-4 + four-step twiddle + store FUSED with f32x2-packed
// twiddles (chained in m0-order, 2 live u64s); (b) stage-A h assigned per-WARP
// (uniform branches, fully coalesced loads). Stage B keeps intra-warp h.
//
// Output: magnitude (32, 513, 1025) fp32.

#define NS        524288
#define BATCHES   32
#define NFRAMES   1025
#define CUTOFF    513
#define HOP       512
#define FPB       8         // frames per block (4 groups x 2 frames)
#define THREADS   256
#define NGROUP    4
#define FULLMASK  0xFFFFFFFFu

#define TSTRIDE   34
#define TILE_F2   (32*TSTRIDE)                  // 1088 float2
#define GSTRIDE   (TILE_F2 + 8)                 // 1096 float2
#define SM_F2     (NGROUP * GSTRIDE)            // 4384
#define SMEM_BYTES (SM_F2 * 8)                  // 35072 B

typedef unsigned long long u64;

__device__ __forceinline__ u64 pk2(float lo, float hi) {
    u64 r; asm("mov.b64 %0, {%1, %2};" : "=l"(r) : "f"(lo), "f"(hi)); return r;
}
__device__ __forceinline__ void upk2(float& lo, float& hi, u64 v) {
    asm("mov.b64 {%0, %1}, %2;" : "=f"(lo), "=f"(hi) : "l"(v));
}
__device__ __forceinline__ u64 add2(u64 a, u64 b) {
    u64 r; asm("add.rn.f32x2 %0, %1, %2;" : "=l"(r) : "l"(a), "l"(b)); return r;
}
__device__ __forceinline__ u64 mul2(u64 a, u64 b) {
    u64 r; asm("mul.rn.f32x2 %0, %1, %2;" : "=l"(r) : "l"(a), "l"(b)); return r;
}
__device__ __forceinline__ u64 fma2(u64 a, u64 b, u64 c) {
    u64 r; asm("fma.rn.f32x2 %0, %1, %2, %3;" : "=l"(r) : "l"(a), "l"(b), "l"(c)); return r;
}

__device__ __forceinline__ constexpr int brev4(int x) {
    return ((x & 1) << 3) | ((x & 2) << 1) | ((x & 4) >> 1) | ((x & 8) >> 3);
}

__device__ __forceinline__ float sqrt_fast(float x) {
    float r;
    asm("sqrt.approx.f32 %0, %1;" : "=f"(r) : "f"(x));
    return r;
}

__device__ __forceinline__ void cmul(float& dr, float& di,
                                     float ar, float ai, float br, float bi) {
    dr = ar * br - ai * bi;
    di = ar * bi + ai * br;
}

// 16-pt tables
#define TC8_0 1.0f
#define TC8_1 0.9238795325f
#define TC8_2 0.7071067812f
#define TC8_3 0.3826834324f
#define TC8_4 0.0f
#define TC8_5 (-0.3826834324f)
#define TC8_6 (-0.7071067812f)
#define TC8_7 (-0.9238795325f)
#define TS8_0 0.0f
#define TS8_1 0.3826834324f
#define TS8_2 0.7071067812f
#define TS8_3 0.9238795325f
#define TS8_4 1.0f
#define TS8_5 0.9238795325f
#define TS8_6 0.7071067812f
#define TS8_7 0.3826834324f

// W32^j = C32[j] - i*S32[j]
__device__ constexpr float C32[16] = {
    1.0f, 0.9807852804f, 0.9238795325f, 0.8314696123f,
    0.7071067812f, 0.5555702330f, 0.3826834324f, 0.1950903220f,
    0.0f, -0.1950903220f, -0.3826834324f, -0.5555702330f,
    -0.7071067812f, -0.8314696123f, -0.9238795325f, -0.9807852804f };
__device__ constexpr float S32[16] = {
    0.0f, 0.1950903220f, 0.3826834324f, 0.5555702330f,
    0.7071067812f, 0.8314696123f, 0.9238795325f, 0.9807852804f,
    1.0f, 0.9807852804f, 0.9238795325f, 0.8314696123f,
    0.7071067812f, 0.5555702330f, 0.3826834324f, 0.1950903220f };

// Packed butterfly: (p, q) pair indices; twiddle applied to the q output.
#define PBFLY(AR, AI, P, Q, C2, S2, NS2, NEG1)                      \
    {   const u64 ur_ = add2(AR[P], AR[Q]);                         \
        const u64 ui_ = add2(AI[P], AI[Q]);                         \
        const u64 vr_ = fma2(AR[Q], NEG1, AR[P]);                   \
        const u64 vi_ = fma2(AI[Q], NEG1, AI[P]);                   \
        AR[P] = ur_; AI[P] = ui_;                                   \
        AR[Q] = fma2(vi_, S2, mul2(vr_, C2));                       \
        AI[Q] = fma2(vr_, NS2, mul2(vi_, C2)); }

// Packed DIF 16-pt FFT, stages 1-3 only (packed state left pre-stage-4).
__device__ __forceinline__ void fft16p_s123(u64 ar2[8], u64 ai2[8]) {
    const u64 NEG1 = pk2(-1.0f, -1.0f);
    {   // stage 1 (half=8)
        const u64 c0 = pk2(TC8_0, TC8_1), s0 = pk2(TS8_0, TS8_1), n0 = pk2(-TS8_0, -TS8_1);
        const u64 c1 = pk2(TC8_2, TC8_3), s1 = pk2(TS8_2, TS8_3), n1 = pk2(-TS8_2, -TS8_3);
        const u64 c2 = pk2(TC8_4, TC8_5), s2 = pk2(TS8_4, TS8_5), n2_ = pk2(-TS8_4, -TS8_5);
        const u64 c3 = pk2(TC8_6, TC8_7), s3 = pk2(TS8_6, TS8_7), n3 = pk2(-TS8_6, -TS8_7);
        PBFLY(ar2, ai2, 0, 4, c0, s0, n0, NEG1);
        PBFLY(ar2, ai2, 1, 5, c1, s1, n1, NEG1);
        PBFLY(ar2, ai2, 2, 6, c2, s2, n2_, NEG1);
        PBFLY(ar2, ai2, 3, 7, c3, s3, n3, NEG1);
    }
    {   // stage 2 (half=4)
        const u64 c0 = pk2(TC8_0, TC8_2), s0 = pk2(TS8_0, TS8_2), n0 = pk2(-TS8_0, -TS8_2);
        const u64 c1 = pk2(TC8_4, TC8_6), s1 = pk2(TS8_4, TS8_6), n1 = pk2(-TS8_4, -TS8_6);
        PBFLY(ar2, ai2, 0, 2, c0, s0, n0, NEG1);
        PBFLY(ar2, ai2, 1, 3, c1, s1, n1, NEG1);
        PBFLY(ar2, ai2, 4, 6, c0, s0, n0, NEG1);
        PBFLY(ar2, ai2, 5, 7, c1, s1, n1, NEG1);
    }
    {   // stage 3 (half=2)
        const u64 c0 = pk2(1.0f, 0.0f), s0 = pk2(0.0f, 1.0f), n0 = pk2(0.0f, -1.0f);
        PBFLY(ar2, ai2, 0, 1, c0, s0, n0, NEG1);
        PBFLY(ar2, ai2, 2, 3, c0, s0, n0, NEG1);
        PBFLY(ar2, ai2, 4, 5, c0, s0, n0, NEG1);
        PBFLY(ar2, ai2, 6, 7, c0, s0, n0, NEG1);
    }
}

// Full packed FFT: stages 1-3 + scalar stage-4 unpack (for stage B).
__device__ __forceinline__ void fft16p(u64 ar2[8], u64 ai2[8],
                                       float ar[16], float ai[16]) {
    fft16p_s123(ar2, ai2);
#pragma unroll
    for (int p = 0; p < 8; ++p) {
        float x0, x1, y0, y1;
        upk2(x0, x1, ar2[p]);
        upk2(y0, y1, ai2[p]);
        ar[2 * p] = x0 + x1;  ar[2 * p + 1] = x0 - x1;
        ai[2 * p] = y0 + y1;  ai[2 * p + 1] = y0 - y1;
    }
}

__device__ __forceinline__ int reflect_idx(int idx) {
    idx = (idx < 0) ? -idx : idx;
    idx = (idx >= NS) ? (2 * NS - 2 - idx) : idx;
    return idx;
}

__global__ void __launch_bounds__(THREADS, 3)
stft_kernel(const float* __restrict__ x, float* __restrict__ out) {
    extern __shared__ float2 sm2[];

    const int tid  = threadIdx.x;
    const int warp = tid >> 5;
    const int lane = tid & 31;
    const int l4   = lane & 15;
    const int hB   = lane >> 4;          // stage-B half-bit (intra-warp)
    const int grp  = warp >> 1;          // 2-warp group = one frame pair
    const int wsub = warp & 1;
    const int hA   = wsub;               // stage-A half-bit (per-warp, uniform)
    float2* tile = sm2 + grp * GSTRIDE;
    float2* magG = tile;                 // UNION: tile dead after stage-B reads

    const int b  = blockIdx.y;
    const int t0 = blockIdx.x * FPB;
    const float* __restrict__ xb = x + (size_t)b * NS;

    const int t = t0 + grp * 2;
    const bool active = (t < NFRAMES);
    const bool interior = (blockIdx.x != 0) && (blockIdx.x != gridDim.x - 1);

    float ar[16], ai[16];
    u64 ar2[8], ai2[8];
    const int n2 = lane;                 // stage-A column (full warp)

    // c0 = cos(pi*n2/512), s0 = sin(pi*n2/512) — MUFU fast path
    float s0, c0;
    __sincosf((float)n2 * 0.00613592315f, &s0, &c0);

    if (active) {
        // ---- stage A, packed over j-pairs; h uniform per warp.
        const int gbase = t * HOP - 512 + n2;
        const float Cs = 0.9807852804f, Ss = 0.1950903220f;   // rot pi/16
        u64 wcc2 = pk2(c0, c0 * Cs - s0 * Ss);
        u64 wss2 = pk2(s0, s0 * Cs + c0 * Ss);
        const u64 CS8  = pk2(0.9238795325f, 0.9238795325f);
        const u64 SS8  = pk2(0.3826834324f, 0.3826834324f);
        const u64 NSS8 = pk2(-0.3826834324f, -0.3826834324f);
        const u64 HALF = pk2(0.5f, 0.5f), NHALF = pk2(-0.5f, -0.5f);
        const u64 NEG1 = pk2(-1.0f, -1.0f);

#pragma unroll
        for (int c4 = 0; c4 < 2; ++c4) {
            u64 X0p[4], X1p[4], X2p[4];
            if (interior) {
#pragma unroll
                for (int jj = 0; jj < 4; ++jj) {
                    const int off = gbase + 64 * (4 * c4 + jj);
                    X0p[jj] = pk2(__ldg(xb + off),        __ldg(xb + off + 32));
                    X1p[jj] = pk2(__ldg(xb + off + 512),  __ldg(xb + off + 544));
                    X2p[jj] = pk2(__ldg(xb + off + 1024), __ldg(xb + off + 1056));
                }
            } else {
#pragma unroll
                for (int jj = 0; jj < 4; ++jj) {
                    const int off = gbase + 64 * (4 * c4 + jj);
                    X0p[jj] = pk2(__ldg(xb + reflect_idx(off)),
                                  __ldg(xb + reflect_idx(off + 32)));
                    X1p[jj] = pk2(__ldg(xb + reflect_idx(off + 512)),
                                  __ldg(xb + reflect_idx(off + 544)));
                    X2p[jj] = pk2(__ldg(xb + reflect_idx(off + 1024)),
                                  __ldg(xb + reflect_idx(off + 1056)));
                }
            }
#pragma unroll
            for (int jj = 0; jj < 4; ++jj) {
                const int jp = 4 * c4 + jj;
                const int j0 = 2 * jp, j1 = j0 + 1;
                const u64 wm2 = fma2(wcc2, NHALF, HALF);   // 0.5 - 0.5*cos
                const u64 wp2 = fma2(wcc2, HALF, HALF);    // 0.5 + 0.5*cos
                const u64 z0r = mul2(wm2, X0p[jj]);
                const u64 z0i = mul2(wm2, X1p[jj]);
                const u64 z1r = mul2(wp2, X1p[jj]);
                const u64 z1i = mul2(wp2, X2p[jj]);
                if (hA == 0) {                     // uniform branch per warp
                    ar2[jp] = add2(z0r, z1r);
                    ai2[jp] = add2(z0i, z1i);
                } else {
                    const u64 vr = fma2(z1r, NEG1, z0r);
                    const u64 vi = fma2(z1i, NEG1, z0i);
                    const u64 c2  = pk2(C32[j0], C32[j1]);
                    const u64 s2  = pk2(S32[j0], S32[j1]);
                    const u64 ns2 = pk2(-S32[j0], -S32[j1]);
                    ar2[jp] = fma2(vi, s2, mul2(vr, c2));
                    ai2[jp] = fma2(vr, ns2, mul2(vi, c2));
                }
                const u64 nc = fma2(wss2, NSS8, mul2(wcc2, CS8));
                wss2 = fma2(wcc2, SS8, mul2(wss2, CS8));
                wcc2 = nc;
            }
        }
        fft16p_s123(ar2, ai2);   // packed pre-stage-4 state

        // ---- FUSED stage-4 + twiddle + store, packed twiddles.
        // Register p holds (X[m0], X[m0+8]) after its local butterfly,
        // m0 = brev4(2p). Twiddle t_m = W1024^{n2(2m+h)}; T[p] = (t_m0, t_m0·W^{16n2}).
        // Iterate in m0-order: chain step multiplies T by W^{2n2} (4 packed ops).
        {
            // seeds: b = W^{2n2}, b8 = W^{16n2} (by squaring)
            float b1r, b1i, b2r, b2i, b4r, b4i, b8r, b8i;
            cmul(b1r, b1i, c0, -s0, c0, -s0);      // W^2n2
            cmul(b2r, b2i, b1r, b1i, b1r, b1i);    // W^4n2
            cmul(b4r, b4i, b2r, b2i, b2r, b2i);    // W^8n2
            cmul(b8r, b8i, b4r, b4i, b4r, b4i);    // W^16n2
            const float t0r = hA ? c0 : 1.0f;      // t_{m0=0} = W^{n2 h}
            const float t0i = hA ? -s0 : 0.0f;
            float t8r, t8i;
            cmul(t8r, t8i, t0r, t0i, b8r, b8i);    // t_8 = t_0 * W^16n2
            u64 Tr = pk2(t0r, t8r);
            u64 Ti = pk2(t0i, t8i);
            const u64 Br  = pk2(b1r, b1r);
            const u64 Bi  = pk2(b1i, b1i);
            const u64 BNi = pk2(-b1i, -b1i);
            const u64 NEG1c = pk2(-1.0f, -1.0f);

#pragma unroll
            for (int m0 = 0; m0 < 8; ++m0) {
                const int p = brev4(m0) >> 1;      // register holding (X[m0], X[m0+8])
                float lor, hir, loi, hii;
                upk2(lor, hir, ar2[p]);
                upk2(loi, hii, ai2[p]);
                const u64 Ur = pk2(lor + hir, lor - hir);   // (X[m0].re, X[m0+8].re)
                const u64 Ui = pk2(loi + hii, loi - hii);
                const u64 TNi = mul2(Ti, NEG1c);
                const u64 Vr = fma2(Ui, TNi, mul2(Ur, Tr));
                const u64 Vi = fma2(Ui, Tr,  mul2(Ur, Ti));
                float vr0, vr1, vi0, vi1;
                upk2(vr0, vr1, Vr);
                upk2(vi0, vi1, Vi);
                const int k1a = 2 * m0 + hA;
                tile[k1a * TSTRIDE + n2]        = make_float2(vr0, vi0);
                tile[(k1a + 16) * TSTRIDE + n2] = make_float2(vr1, vi1);
                if (m0 < 7) {                      // T *= W^{2n2} (packed)
                    const u64 nTr = fma2(Ti, BNi, mul2(Tr, Br));
                    Ti = fma2(Tr, Bi, mul2(Ti, Br));
                    Tr = nTr;
                }
            }
        }

        // group barrier: tile stores -> tile loads (2 warps, id grp+1)
        asm volatile("bar.sync %0, %1;" :: "r"(grp + 1), "r"(64) : "memory");

        // ---- stage B: k1 -> lane map keeps k1 and 32-k1 in the SAME warp.
        int k1;
        if (wsub == 0) {
            if (l4 == 0)      k1 = 0;
            else if (l4 == 1) k1 = 16;
            else {
                const int p = l4 >> 1;
                k1 = (l4 & 1) ? (32 - p) : p;
            }
        } else {
            const int p = 8 + (l4 >> 1);
            k1 = (l4 & 1) ? (32 - p) : p;
        }

        // vectorized dual-half reads (LDS.128) + PACKED cross butterfly.
        const float4* t4lo = (const float4*)(tile + k1 * TSTRIDE);       // n2v 0..15
        const float4* t4hi = (const float4*)(tile + k1 * TSTRIDE + 16);  // n2v 16..31
        const u64 NEG1b = pk2(-1.0f, -1.0f);
#pragma unroll
        for (int jq = 0; jq < 8; ++jq) {
            const float4 a0 = t4lo[jq];      // (z[2jq].re, .im, z[2jq+1].re, .im)
            const float4 a1 = t4hi[jq];
            const u64 r0 = pk2(a0.x, a0.z), i0 = pk2(a0.y, a0.w);
            const u64 r1 = pk2(a1.x, a1.z), i1 = pk2(a1.y, a1.w);
            if (hB == 0) {                   // u = a0 + a1
                ar2[jq] = add2(r0, r1);
                ai2[jq] = add2(i0, i1);
            } else {                         // v = (a0 - a1) * W32^j
                const u64 vr = fma2(r1, NEG1b, r0);
                const u64 vi = fma2(i1, NEG1b, i0);
                const int j0 = 2 * jq, j1 = 2 * jq + 1;
                const u64 c2  = pk2(C32[j0], C32[j1]);
                const u64 s2  = pk2(S32[j0], S32[j1]);
                const u64 ns2 = pk2(-S32[j0], -S32[j1]);
                ar2[jq] = fma2(vi, s2, mul2(vr, c2));
                ai2[jq] = fma2(vr, ns2, mul2(vi, c2));
            }
        }
        fft16p(ar2, ai2, ar, ai);   // reg r holds Z[k1 + 32*(2*brev4(r) + hB)]

        // group barrier: tile reads done -> magG (union) may be overwritten
        asm volatile("bar.sync %0, %1;" :: "r"(grp + 1), "r"(64) : "memory");

        // ---- conjugate-symmetry unpack + magnitudes.
        const bool k1zero = (wsub == 0) && (l4 == 0);
        const bool k1mid  = (wsub == 0) && (l4 == 1);
        const int msk = k1zero ? 0 : (k1mid ? 16 : 17);
        constexpr int TBL[8] = { 0, 3, 7, 5, 15, 13, 11, 9 };
        float qr_[8], qi_[8];
#pragma unroll
        for (int ri = 0; ri < 8; ++ri) {        // batch all unpack shuffles
            qr_[ri] = __shfl_xor_sync(FULLMASK, ar[15 - 2 * ri], msk);
            qi_[ri] = __shfl_xor_sync(FULLMASK, ai[15 - 2 * ri], msk);
        }
#pragma unroll
        for (int ri = 0; ri < 8; ++ri) {
            const int r = 2 * ri;
            float qr = qr_[ri], qi = qi_[ri];
            if (k1zero && hB == 0) { qr = ar[TBL[ri]]; qi = ai[TBL[ri]]; }
            const float zr = ar[r], zi = ai[r];
            const float e0r = zr + qr, e0i = zi - qi;   // X_t[k]     * 2
            const float e1r = zr - qr, e1i = zi + qi;   // X_{t+1}[k] * 2i
            const float m0 = 0.5f * sqrt_fast(e0r * e0r + e0i * e0i);
            const float m1 = 0.5f * sqrt_fast(e1r * e1r + e1i * e1i);
            const int k2 = 2 * brev4(r) + hB;
            const int k  = k1 + 32 * k2;
            magG[k] = make_float2(m0, m1);              // STS.64 into union
        }
        if (k1zero && hB == 0) {   // k = 512 lives at reg 1 (k2 = 16)
            magG[512] = make_float2(fabsf(ar[1]), fabsf(ai[1]));
        }
    }
    __syncthreads();

    // ---- writeback: thread -> (k, group); predicates only on the last block
    const size_t obase = (size_t)b * CUTOFF * NFRAMES;
    if (blockIdx.x != gridDim.x - 1) {
        for (int i = tid; i < CUTOFF * NGROUP; i += THREADS) {   // 513*4 = 2052
            const int k = i >> 2;
            const int g = i & 3;
            const float2 v = sm2[g * GSTRIDE + k];
            float* orow = out + obase + (size_t)k * NFRAMES + t0 + 2 * g;
            orow[0] = v.x;
            orow[1] = v.y;
        }
    } else {
        for (int i = tid; i < CUTOFF * NGROUP; i += THREADS) {
            const int k = i >> 2;
            const int g = i & 3;
            const float2 v = sm2[g * GSTRIDE + k];
            const int tt = t0 + 2 * g;
            float* orow = out + obase + (size_t)k * NFRAMES;
            if (tt < NFRAMES)     orow[tt] = v.x;
            if (tt + 1 < NFRAMES) orow[tt + 1] = v.y;
        }
    }
}

extern "C" void kernel_launch(void* const* d_in, const int* in_sizes, int n_in,
                              void* d_out, int out_size) {
    const float* x = (const float*)d_in[0];
    // d_in[1] = forward_basis: identical to our windowed DFT; unused.
    float* out = (float*)d_out;

    cudaFuncSetAttribute(stft_kernel,
                         cudaFuncAttributeMaxDynamicSharedMemorySize, SMEM_BYTES);

    dim3 grid((NFRAMES + FPB - 1) / FPB, BATCHES);
    stft_kernel<<<grid, THREADS, SMEM_BYTES>>>(x, out);
}

// round 16
// speedup vs baseline: 1.5703x; 1.5703x over previous
#include <cuda_runtime.h>
#include <cstddef>

// STFT via four-step FFT (1024 = 32x32), real-pair packed, 2 lanes per 32-pt FFT.
// Round-16 = R14 (best: 68.4us) + stage-A h per-WARP only (uniform branches,
// 128B-coalesced loads). The R15 stage-4/twiddle fusion is REVERTED (it caused
// a pk2/upk2 register-pair MOV storm: +50% issued instructions).
//
// Output: magnitude (32, 513, 1025) fp32.

#define NS        524288
#define BATCHES   32
#define NFRAMES   1025
#define CUTOFF    513
#define HOP       512
#define FPB       8         // frames per block (4 groups x 2 frames)
#define THREADS   256
#define NGROUP    4
#define FULLMASK  0xFFFFFFFFu

#define TSTRIDE   34
#define TILE_F2   (32*TSTRIDE)                  // 1088 float2
#define GSTRIDE   (TILE_F2 + 8)                 // 1096 float2
#define SM_F2     (NGROUP * GSTRIDE)            // 4384
#define SMEM_BYTES (SM_F2 * 8)                  // 35072 B

typedef unsigned long long u64;

__device__ __forceinline__ u64 pk2(float lo, float hi) {
    u64 r; asm("mov.b64 %0, {%1, %2};" : "=l"(r) : "f"(lo), "f"(hi)); return r;
}
__device__ __forceinline__ void upk2(float& lo, float& hi, u64 v) {
    asm("mov.b64 {%0, %1}, %2;" : "=f"(lo), "=f"(hi) : "l"(v));
}
__device__ __forceinline__ u64 add2(u64 a, u64 b) {
    u64 r; asm("add.rn.f32x2 %0, %1, %2;" : "=l"(r) : "l"(a), "l"(b)); return r;
}
__device__ __forceinline__ u64 mul2(u64 a, u64 b) {
    u64 r; asm("mul.rn.f32x2 %0, %1, %2;" : "=l"(r) : "l"(a), "l"(b)); return r;
}
__device__ __forceinline__ u64 fma2(u64 a, u64 b, u64 c) {
    u64 r; asm("fma.rn.f32x2 %0, %1, %2, %3;" : "=l"(r) : "l"(a), "l"(b), "l"(c)); return r;
}

__device__ __forceinline__ constexpr int brev4(int x) {
    return ((x & 1) << 3) | ((x & 2) << 1) | ((x & 4) >> 1) | ((x & 8) >> 3);
}

__device__ __forceinline__ float sqrt_fast(float x) {
    float r;
    asm("sqrt.approx.f32 %0, %1;" : "=f"(r) : "f"(x));
    return r;
}

__device__ __forceinline__ void cmul(float& dr, float& di,
                                     float ar, float ai, float br, float bi) {
    dr = ar * br - ai * bi;
    di = ar * bi + ai * br;
}

// 16-pt tables
#define TC8_0 1.0f
#define TC8_1 0.9238795325f
#define TC8_2 0.7071067812f
#define TC8_3 0.3826834324f
#define TC8_4 0.0f
#define TC8_5 (-0.3826834324f)
#define TC8_6 (-0.7071067812f)
#define TC8_7 (-0.9238795325f)
#define TS8_0 0.0f
#define TS8_1 0.3826834324f
#define TS8_2 0.7071067812f
#define TS8_3 0.9238795325f
#define TS8_4 1.0f
#define TS8_5 0.9238795325f
#define TS8_6 0.7071067812f
#define TS8_7 0.3826834324f

// W32^j = C32[j] - i*S32[j]
__device__ constexpr float C32[16] = {
    1.0f, 0.9807852804f, 0.9238795325f, 0.8314696123f,
    0.7071067812f, 0.5555702330f, 0.3826834324f, 0.1950903220f,
    0.0f, -0.1950903220f, -0.3826834324f, -0.5555702330f,
    -0.7071067812f, -0.8314696123f, -0.9238795325f, -0.9807852804f };
__device__ constexpr float S32[16] = {
    0.0f, 0.1950903220f, 0.3826834324f, 0.5555702330f,
    0.7071067812f, 0.8314696123f, 0.9238795325f, 0.9807852804f,
    1.0f, 0.9807852804f, 0.9238795325f, 0.8314696123f,
    0.7071067812f, 0.5555702330f, 0.3826834324f, 0.1950903220f };

// Packed butterfly: (p, q) pair indices; twiddle applied to the q output.
#define PBFLY(AR, AI, P, Q, C2, S2, NS2, NEG1)                      \
    {   const u64 ur_ = add2(AR[P], AR[Q]);                         \
        const u64 ui_ = add2(AI[P], AI[Q]);                         \
        const u64 vr_ = fma2(AR[Q], NEG1, AR[P]);                   \
        const u64 vi_ = fma2(AI[Q], NEG1, AI[P]);                   \
        AR[P] = ur_; AI[P] = ui_;                                   \
        AR[Q] = fma2(vi_, S2, mul2(vr_, C2));                       \
        AI[Q] = fma2(vr_, NS2, mul2(vi_, C2)); }

// Packed DIF 16-pt FFT. Input: ar2[p] = (x[2p], x[2p+1]). Output scalar,
// bit-reversed: ar[r] = X[brev4(r)].
__device__ __forceinline__ void fft16p(u64 ar2[8], u64 ai2[8],
                                       float ar[16], float ai[16]) {
    const u64 NEG1 = pk2(-1.0f, -1.0f);
    {   // stage 1 (half=8)
        const u64 c0 = pk2(TC8_0, TC8_1), s0 = pk2(TS8_0, TS8_1), n0 = pk2(-TS8_0, -TS8_1);
        const u64 c1 = pk2(TC8_2, TC8_3), s1 = pk2(TS8_2, TS8_3), n1 = pk2(-TS8_2, -TS8_3);
        const u64 c2 = pk2(TC8_4, TC8_5), s2 = pk2(TS8_4, TS8_5), n2_ = pk2(-TS8_4, -TS8_5);
        const u64 c3 = pk2(TC8_6, TC8_7), s3 = pk2(TS8_6, TS8_7), n3 = pk2(-TS8_6, -TS8_7);
        PBFLY(ar2, ai2, 0, 4, c0, s0, n0, NEG1);
        PBFLY(ar2, ai2, 1, 5, c1, s1, n1, NEG1);
        PBFLY(ar2, ai2, 2, 6, c2, s2, n2_, NEG1);
        PBFLY(ar2, ai2, 3, 7, c3, s3, n3, NEG1);
    }
    {   // stage 2 (half=4)
        const u64 c0 = pk2(TC8_0, TC8_2), s0 = pk2(TS8_0, TS8_2), n0 = pk2(-TS8_0, -TS8_2);
        const u64 c1 = pk2(TC8_4, TC8_6), s1 = pk2(TS8_4, TS8_6), n1 = pk2(-TS8_4, -TS8_6);
        PBFLY(ar2, ai2, 0, 2, c0, s0, n0, NEG1);
        PBFLY(ar2, ai2, 1, 3, c1, s1, n1, NEG1);
        PBFLY(ar2, ai2, 4, 6, c0, s0, n0, NEG1);
        PBFLY(ar2, ai2, 5, 7, c1, s1, n1, NEG1);
    }
    {   // stage 3 (half=2)
        const u64 c0 = pk2(1.0f, 0.0f), s0 = pk2(0.0f, 1.0f), n0 = pk2(0.0f, -1.0f);
        PBFLY(ar2, ai2, 0, 1, c0, s0, n0, NEG1);
        PBFLY(ar2, ai2, 2, 3, c0, s0, n0, NEG1);
        PBFLY(ar2, ai2, 4, 5, c0, s0, n0, NEG1);
        PBFLY(ar2, ai2, 6, 7, c0, s0, n0, NEG1);
    }
    // stage 4 (half=1, twiddle-free): intra-pair scalar butterfly = unpack
#pragma unroll
    for (int p = 0; p < 8; ++p) {
        float x0, x1, y0, y1;
        upk2(x0, x1, ar2[p]);
        upk2(y0, y1, ai2[p]);
        ar[2 * p] = x0 + x1;  ar[2 * p + 1] = x0 - x1;
        ai[2 * p] = y0 + y1;  ai[2 * p + 1] = y0 - y1;
    }
}

__device__ __forceinline__ int reflect_idx(int idx) {
    idx = (idx < 0) ? -idx : idx;
    idx = (idx >= NS) ? (2 * NS - 2 - idx) : idx;
    return idx;
}

__global__ void __launch_bounds__(THREADS, 3)
stft_kernel(const float* __restrict__ x, float* __restrict__ out) {
    extern __shared__ float2 sm2[];

    const int tid  = threadIdx.x;
    const int warp = tid >> 5;
    const int lane = tid & 31;
    const int l4   = lane & 15;
    const int hB   = lane >> 4;          // stage-B half-bit (intra-warp)
    const int grp  = warp >> 1;          // 2-warp group = one frame pair
    const int wsub = warp & 1;
    const int hA   = wsub;               // stage-A half-bit (per-warp, uniform)
    float2* tile = sm2 + grp * GSTRIDE;
    float2* magG = tile;                 // UNION: tile dead after stage-B reads

    const int b  = blockIdx.y;
    const int t0 = blockIdx.x * FPB;
    const float* __restrict__ xb = x + (size_t)b * NS;

    const int t = t0 + grp * 2;
    const bool active = (t < NFRAMES);
    const bool interior = (blockIdx.x != 0) && (blockIdx.x != gridDim.x - 1);

    float ar[16], ai[16];
    u64 ar2[8], ai2[8];
    const int n2 = lane;                 // stage-A column (full warp)

    // c0 = cos(pi*n2/512), s0 = sin(pi*n2/512) — MUFU fast path
    float s0, c0;
    __sincosf((float)n2 * 0.00613592315f, &s0, &c0);

    if (active) {
        // ---- stage A, packed over j-pairs; h uniform per warp, n2 = lane.
        const int gbase = t * HOP - 512 + n2;
        const float Cs = 0.9807852804f, Ss = 0.1950903220f;   // rot pi/16
        u64 wcc2 = pk2(c0, c0 * Cs - s0 * Ss);
        u64 wss2 = pk2(s0, s0 * Cs + c0 * Ss);
        const u64 CS8  = pk2(0.9238795325f, 0.9238795325f);
        const u64 SS8  = pk2(0.3826834324f, 0.3826834324f);
        const u64 NSS8 = pk2(-0.3826834324f, -0.3826834324f);
        const u64 HALF = pk2(0.5f, 0.5f), NHALF = pk2(-0.5f, -0.5f);
        const u64 NEG1 = pk2(-1.0f, -1.0f);

#pragma unroll
        for (int c4 = 0; c4 < 2; ++c4) {
            u64 X0p[4], X1p[4], X2p[4];
            if (interior) {
#pragma unroll
                for (int jj = 0; jj < 4; ++jj) {
                    const int off = gbase + 64 * (4 * c4 + jj);
                    X0p[jj] = pk2(__ldg(xb + off),        __ldg(xb + off + 32));
                    X1p[jj] = pk2(__ldg(xb + off + 512),  __ldg(xb + off + 544));
                    X2p[jj] = pk2(__ldg(xb + off + 1024), __ldg(xb + off + 1056));
                }
            } else {
#pragma unroll
                for (int jj = 0; jj < 4; ++jj) {
                    const int off = gbase + 64 * (4 * c4 + jj);
                    X0p[jj] = pk2(__ldg(xb + reflect_idx(off)),
                                  __ldg(xb + reflect_idx(off + 32)));
                    X1p[jj] = pk2(__ldg(xb + reflect_idx(off + 512)),
                                  __ldg(xb + reflect_idx(off + 544)));
                    X2p[jj] = pk2(__ldg(xb + reflect_idx(off + 1024)),
                                  __ldg(xb + reflect_idx(off + 1056)));
                }
            }
#pragma unroll
            for (int jj = 0; jj < 4; ++jj) {
                const int jp = 4 * c4 + jj;
                const int j0 = 2 * jp, j1 = j0 + 1;
                const u64 wm2 = fma2(wcc2, NHALF, HALF);   // 0.5 - 0.5*cos
                const u64 wp2 = fma2(wcc2, HALF, HALF);    // 0.5 + 0.5*cos
                const u64 z0r = mul2(wm2, X0p[jj]);
                const u64 z0i = mul2(wm2, X1p[jj]);
                const u64 z1r = mul2(wp2, X1p[jj]);
                const u64 z1i = mul2(wp2, X2p[jj]);
                if (hA == 0) {                     // uniform branch per warp
                    ar2[jp] = add2(z0r, z1r);
                    ai2[jp] = add2(z0i, z1i);
                } else {
                    const u64 vr = fma2(z1r, NEG1, z0r);
                    const u64 vi = fma2(z1i, NEG1, z0i);
                    const u64 c2  = pk2(C32[j0], C32[j1]);
                    const u64 s2  = pk2(S32[j0], S32[j1]);
                    const u64 ns2 = pk2(-S32[j0], -S32[j1]);
                    ar2[jp] = fma2(vi, s2, mul2(vr, c2));
                    ai2[jp] = fma2(vr, ns2, mul2(vi, c2));
                }
                const u64 nc = fma2(wss2, NSS8, mul2(wcc2, CS8));
                wss2 = fma2(wcc2, SS8, mul2(wss2, CS8));
                wcc2 = nc;
            }
        }
        fft16p(ar2, ai2, ar, ai);   // reg r holds A[n2, k1 = 2*brev4(r) + hA]

        // ---- twiddle by W1024^{n2*k1}, k1 = 2m + hA, m = 4q + p (R14 scalar form).
        float w2r, w2i, w4r, w4i, w6r, w6i, w8r, w8i;
        cmul(w2r, w2i, c0, -s0, c0, -s0);          // W^2n2
        cmul(w4r, w4i, w2r, w2i, w2r, w2i);        // W^4n2
        cmul(w6r, w6i, w2r, w2i, w4r, w4i);        // W^6n2
        cmul(w8r, w8i, w4r, w4i, w4r, w4i);        // W^8n2
        const float br = hA ? c0 : 1.0f;
        const float bi = hA ? -s0 : 0.0f;
        float cr[4], ci[4];
        cr[0] = br;  ci[0] = bi;
        cmul(cr[1], ci[1], br, bi, w2r, w2i);
        cmul(cr[2], ci[2], br, bi, w4r, w4i);
        cmul(cr[3], ci[3], br, bi, w6r, w6i);

#pragma unroll
        for (int q = 0; q < 4; ++q) {
#pragma unroll
            for (int p = 0; p < 4; ++p) {
                const int m  = 4 * q + p;
                const int r  = brev4(m);
                const int k1 = 2 * m + hA;
                float vr, vi;
                cmul(vr, vi, ar[r], ai[r], cr[p], ci[p]);
                tile[k1 * TSTRIDE + n2] = make_float2(vr, vi);   // STS.64
                if (q < 3) {
                    float nr, ni;
                    cmul(nr, ni, cr[p], ci[p], w8r, w8i);
                    cr[p] = nr; ci[p] = ni;
                }
            }
        }

        // group barrier: tile stores -> tile loads (2 warps, id grp+1)
        asm volatile("bar.sync %0, %1;" :: "r"(grp + 1), "r"(64) : "memory");

        // ---- stage B: k1 -> lane map keeps k1 and 32-k1 in the SAME warp.
        int k1;
        if (wsub == 0) {
            if (l4 == 0)      k1 = 0;
            else if (l4 == 1) k1 = 16;
            else {
                const int p = l4 >> 1;
                k1 = (l4 & 1) ? (32 - p) : p;
            }
        } else {
            const int p = 8 + (l4 >> 1);
            k1 = (l4 & 1) ? (32 - p) : p;
        }

        // vectorized dual-half reads (LDS.128) + PACKED cross butterfly.
        const float4* t4lo = (const float4*)(tile + k1 * TSTRIDE);       // n2v 0..15
        const float4* t4hi = (const float4*)(tile + k1 * TSTRIDE + 16);  // n2v 16..31
        const u64 NEG1b = pk2(-1.0f, -1.0f);
#pragma unroll
        for (int jq = 0; jq < 8; ++jq) {
            const float4 a0 = t4lo[jq];      // (z[2jq].re, .im, z[2jq+1].re, .im)
            const float4 a1 = t4hi[jq];
            const u64 r0 = pk2(a0.x, a0.z), i0 = pk2(a0.y, a0.w);
            const u64 r1 = pk2(a1.x, a1.z), i1 = pk2(a1.y, a1.w);
            if (hB == 0) {                   // u = a0 + a1
                ar2[jq] = add2(r0, r1);
                ai2[jq] = add2(i0, i1);
            } else {                         // v = (a0 - a1) * W32^j
                const u64 vr = fma2(r1, NEG1b, r0);
                const u64 vi = fma2(i1, NEG1b, i0);
                const int j0 = 2 * jq, j1 = 2 * jq + 1;
                const u64 c2  = pk2(C32[j0], C32[j1]);
                const u64 s2  = pk2(S32[j0], S32[j1]);
                const u64 ns2 = pk2(-S32[j0], -S32[j1]);
                ar2[jq] = fma2(vi, s2, mul2(vr, c2));
                ai2[jq] = fma2(vr, ns2, mul2(vi, c2));
            }
        }
        fft16p(ar2, ai2, ar, ai);   // reg r holds Z[k1 + 32*(2*brev4(r) + hB)]

        // group barrier: tile reads done -> magG (union) may be overwritten
        asm volatile("bar.sync %0, %1;" :: "r"(grp + 1), "r"(64) : "memory");

        // ---- conjugate-symmetry unpack + magnitudes.
        const bool k1zero = (wsub == 0) && (l4 == 0);
        const bool k1mid  = (wsub == 0) && (l4 == 1);
        const int msk = k1zero ? 0 : (k1mid ? 16 : 17);
        constexpr int TBL[8] = { 0, 3, 7, 5, 15, 13, 11, 9 };
        float qr_[8], qi_[8];
#pragma unroll
        for (int ri = 0; ri < 8; ++ri) {        // batch all unpack shuffles
            qr_[ri] = __shfl_xor_sync(FULLMASK, ar[15 - 2 * ri], msk);
            qi_[ri] = __shfl_xor_sync(FULLMASK, ai[15 - 2 * ri], msk);
        }
#pragma unroll
        for (int ri = 0; ri < 8; ++ri) {
            const int r = 2 * ri;
            float qr = qr_[ri], qi = qi_[ri];
            if (k1zero && hB == 0) { qr = ar[TBL[ri]]; qi = ai[TBL[ri]]; }
            const float zr = ar[r], zi = ai[r];
            const float e0r = zr + qr, e0i = zi - qi;   // X_t[k]     * 2
            const float e1r = zr - qr, e1i = zi + qi;   // X_{t+1}[k] * 2i
            const float m0 = 0.5f * sqrt_fast(e0r * e0r + e0i * e0i);
            const float m1 = 0.5f * sqrt_fast(e1r * e1r + e1i * e1i);
            const int k2 = 2 * brev4(r) + hB;
            const int k  = k1 + 32 * k2;
            magG[k] = make_float2(m0, m1);              // STS.64 into union
        }
        if (k1zero && hB == 0) {   // k = 512 lives at reg 1 (k2 = 16)
            magG[512] = make_float2(fabsf(ar[1]), fabsf(ai[1]));
        }
    }
    __syncthreads();

    // ---- writeback: thread -> (k, group); predicates only on the last block
    const size_t obase = (size_t)b * CUTOFF * NFRAMES;
    if (blockIdx.x != gridDim.x - 1) {
        for (int i = tid; i < CUTOFF * NGROUP; i += THREADS) {   // 513*4 = 2052
            const int k = i >> 2;
            const int g = i & 3;
            const float2 v = sm2[g * GSTRIDE + k];
            float* orow = out + obase + (size_t)k * NFRAMES + t0 + 2 * g;
            orow[0] = v.x;
            orow[1] = v.y;
        }
    } else {
        for (int i = tid; i < CUTOFF * NGROUP; i += THREADS) {
            const int k = i >> 2;
            const int g = i & 3;
            const float2 v = sm2[g * GSTRIDE + k];
            const int tt = t0 + 2 * g;
            float* orow = out + obase + (size_t)k * NFRAMES;
            if (tt < NFRAMES)     orow[tt] = v.x;
            if (tt + 1 < NFRAMES) orow[tt + 1] = v.y;
        }
    }
}

extern "C" void kernel_launch(void* const* d_in, const int* in_sizes, int n_in,
                              void* d_out, int out_size) {
    const float* x = (const float*)d_in[0];
    // d_in[1] = forward_basis: identical to our windowed DFT; unused.
    float* out = (float*)d_out;

    cudaFuncSetAttribute(stft_kernel,
                         cudaFuncAttributeMaxDynamicSharedMemorySize, SMEM_BYTES);

    dim3 grid((NFRAMES + FPB - 1) / FPB, BATCHES);
    stft_kernel<<<grid, THREADS, SMEM_BYTES>>>(x, out);
}

// round 17
// speedup vs baseline: 1.6008x; 1.0194x over previous
#include <cuda_runtime.h>
#include <cstddef>

// STFT via four-step FFT (1024 = 32x32), real-pair packed, 2 lanes per 32-pt FFT.
// Round-17 = R16 + occupancy: __launch_bounds__(256,4) (64-reg cap -> 32 warps/SM),
// with stage-A load chunks narrowed to 2-wide so the packed state fits 64 regs
// without spilling. Latency-exposure theory: lean stream + more warps -> issue up.
//
// Output: magnitude (32, 513, 1025) fp32.

#define NS        524288
#define BATCHES   32
#define NFRAMES   1025
#define CUTOFF    513
#define HOP       512
#define FPB       8         // frames per block (4 groups x 2 frames)
#define THREADS   256
#define NGROUP    4
#define FULLMASK  0xFFFFFFFFu

#define TSTRIDE   34
#define TILE_F2   (32*TSTRIDE)                  // 1088 float2
#define GSTRIDE   (TILE_F2 + 8)                 // 1096 float2
#define SM_F2     (NGROUP * GSTRIDE)            // 4384
#define SMEM_BYTES (SM_F2 * 8)                  // 35072 B -> 4 blocks/SM fits smem

typedef unsigned long long u64;

__device__ __forceinline__ u64 pk2(float lo, float hi) {
    u64 r; asm("mov.b64 %0, {%1, %2};" : "=l"(r) : "f"(lo), "f"(hi)); return r;
}
__device__ __forceinline__ void upk2(float& lo, float& hi, u64 v) {
    asm("mov.b64 {%0, %1}, %2;" : "=f"(lo), "=f"(hi) : "l"(v));
}
__device__ __forceinline__ u64 add2(u64 a, u64 b) {
    u64 r; asm("add.rn.f32x2 %0, %1, %2;" : "=l"(r) : "l"(a), "l"(b)); return r;
}
__device__ __forceinline__ u64 mul2(u64 a, u64 b) {
    u64 r; asm("mul.rn.f32x2 %0, %1, %2;" : "=l"(r) : "l"(a), "l"(b)); return r;
}
__device__ __forceinline__ u64 fma2(u64 a, u64 b, u64 c) {
    u64 r; asm("fma.rn.f32x2 %0, %1, %2, %3;" : "=l"(r) : "l"(a), "l"(b), "l"(c)); return r;
}

__device__ __forceinline__ constexpr int brev4(int x) {
    return ((x & 1) << 3) | ((x & 2) << 1) | ((x & 4) >> 1) | ((x & 8) >> 3);
}

__device__ __forceinline__ float sqrt_fast(float x) {
    float r;
    asm("sqrt.approx.f32 %0, %1;" : "=f"(r) : "f"(x));
    return r;
}

__device__ __forceinline__ void cmul(float& dr, float& di,
                                     float ar, float ai, float br, float bi) {
    dr = ar * br - ai * bi;
    di = ar * bi + ai * br;
}

// 16-pt tables
#define TC8_0 1.0f
#define TC8_1 0.9238795325f
#define TC8_2 0.7071067812f
#define TC8_3 0.3826834324f
#define TC8_4 0.0f
#define TC8_5 (-0.3826834324f)
#define TC8_6 (-0.7071067812f)
#define TC8_7 (-0.9238795325f)
#define TS8_0 0.0f
#define TS8_1 0.3826834324f
#define TS8_2 0.7071067812f
#define TS8_3 0.9238795325f
#define TS8_4 1.0f
#define TS8_5 0.9238795325f
#define TS8_6 0.7071067812f
#define TS8_7 0.3826834324f

// W32^j = C32[j] - i*S32[j]
__device__ constexpr float C32[16] = {
    1.0f, 0.9807852804f, 0.9238795325f, 0.8314696123f,
    0.7071067812f, 0.5555702330f, 0.3826834324f, 0.1950903220f,
    0.0f, -0.1950903220f, -0.3826834324f, -0.5555702330f,
    -0.7071067812f, -0.8314696123f, -0.9238795325f, -0.9807852804f };
__device__ constexpr float S32[16] = {
    0.0f, 0.1950903220f, 0.3826834324f, 0.5555702330f,
    0.7071067812f, 0.8314696123f, 0.9238795325f, 0.9807852804f,
    1.0f, 0.9807852804f, 0.9238795325f, 0.8314696123f,
    0.7071067812f, 0.5555702330f, 0.3826834324f, 0.1950903220f };

// Packed butterfly: (p, q) pair indices; twiddle applied to the q output.
#define PBFLY(AR, AI, P, Q, C2, S2, NS2, NEG1)                      \
    {   const u64 ur_ = add2(AR[P], AR[Q]);                         \
        const u64 ui_ = add2(AI[P], AI[Q]);                         \
        const u64 vr_ = fma2(AR[Q], NEG1, AR[P]);                   \
        const u64 vi_ = fma2(AI[Q], NEG1, AI[P]);                   \
        AR[P] = ur_; AI[P] = ui_;                                   \
        AR[Q] = fma2(vi_, S2, mul2(vr_, C2));                       \
        AI[Q] = fma2(vr_, NS2, mul2(vi_, C2)); }

// Packed DIF 16-pt FFT. Input: ar2[p] = (x[2p], x[2p+1]). Output scalar,
// bit-reversed: ar[r] = X[brev4(r)].
__device__ __forceinline__ void fft16p(u64 ar2[8], u64 ai2[8],
                                       float ar[16], float ai[16]) {
    const u64 NEG1 = pk2(-1.0f, -1.0f);
    {   // stage 1 (half=8)
        const u64 c0 = pk2(TC8_0, TC8_1), s0 = pk2(TS8_0, TS8_1), n0 = pk2(-TS8_0, -TS8_1);
        const u64 c1 = pk2(TC8_2, TC8_3), s1 = pk2(TS8_2, TS8_3), n1 = pk2(-TS8_2, -TS8_3);
        const u64 c2 = pk2(TC8_4, TC8_5), s2 = pk2(TS8_4, TS8_5), n2_ = pk2(-TS8_4, -TS8_5);
        const u64 c3 = pk2(TC8_6, TC8_7), s3 = pk2(TS8_6, TS8_7), n3 = pk2(-TS8_6, -TS8_7);
        PBFLY(ar2, ai2, 0, 4, c0, s0, n0, NEG1);
        PBFLY(ar2, ai2, 1, 5, c1, s1, n1, NEG1);
        PBFLY(ar2, ai2, 2, 6, c2, s2, n2_, NEG1);
        PBFLY(ar2, ai2, 3, 7, c3, s3, n3, NEG1);
    }
    {   // stage 2 (half=4)
        const u64 c0 = pk2(TC8_0, TC8_2), s0 = pk2(TS8_0, TS8_2), n0 = pk2(-TS8_0, -TS8_2);
        const u64 c1 = pk2(TC8_4, TC8_6), s1 = pk2(TS8_4, TS8_6), n1 = pk2(-TS8_4, -TS8_6);
        PBFLY(ar2, ai2, 0, 2, c0, s0, n0, NEG1);
        PBFLY(ar2, ai2, 1, 3, c1, s1, n1, NEG1);
        PBFLY(ar2, ai2, 4, 6, c0, s0, n0, NEG1);
        PBFLY(ar2, ai2, 5, 7, c1, s1, n1, NEG1);
    }
    {   // stage 3 (half=2)
        const u64 c0 = pk2(1.0f, 0.0f), s0 = pk2(0.0f, 1.0f), n0 = pk2(0.0f, -1.0f);
        PBFLY(ar2, ai2, 0, 1, c0, s0, n0, NEG1);
        PBFLY(ar2, ai2, 2, 3, c0, s0, n0, NEG1);
        PBFLY(ar2, ai2, 4, 5, c0, s0, n0, NEG1);
        PBFLY(ar2, ai2, 6, 7, c0, s0, n0, NEG1);
    }
    // stage 4 (half=1, twiddle-free): intra-pair scalar butterfly = unpack
#pragma unroll
    for (int p = 0; p < 8; ++p) {
        float x0, x1, y0, y1;
        upk2(x0, x1, ar2[p]);
        upk2(y0, y1, ai2[p]);
        ar[2 * p] = x0 + x1;  ar[2 * p + 1] = x0 - x1;
        ai[2 * p] = y0 + y1;  ai[2 * p + 1] = y0 - y1;
    }
}

__device__ __forceinline__ int reflect_idx(int idx) {
    idx = (idx < 0) ? -idx : idx;
    idx = (idx >= NS) ? (2 * NS - 2 - idx) : idx;
    return idx;
}

__global__ void __launch_bounds__(THREADS, 4)
stft_kernel(const float* __restrict__ x, float* __restrict__ out) {
    extern __shared__ float2 sm2[];

    const int tid  = threadIdx.x;
    const int warp = tid >> 5;
    const int lane = tid & 31;
    const int l4   = lane & 15;
    const int hB   = lane >> 4;          // stage-B half-bit (intra-warp)
    const int grp  = warp >> 1;          // 2-warp group = one frame pair
    const int wsub = warp & 1;
    const int hA   = wsub;               // stage-A half-bit (per-warp, uniform)
    float2* tile = sm2 + grp * GSTRIDE;
    float2* magG = tile;                 // UNION: tile dead after stage-B reads

    const int b  = blockIdx.y;
    const int t0 = blockIdx.x * FPB;
    const float* __restrict__ xb = x + (size_t)b * NS;

    const int t = t0 + grp * 2;
    const bool active = (t < NFRAMES);
    const bool interior = (blockIdx.x != 0) && (blockIdx.x != gridDim.x - 1);

    float ar[16], ai[16];
    u64 ar2[8], ai2[8];
    const int n2 = lane;                 // stage-A column (full warp)

    // c0 = cos(pi*n2/512), s0 = sin(pi*n2/512) — MUFU fast path
    float s0, c0;
    __sincosf((float)n2 * 0.00613592315f, &s0, &c0);

    if (active) {
        // ---- stage A, packed over j-pairs; h uniform per warp, n2 = lane.
        // Loads chunked 2-wide (6 u64 live) to hold peak pressure under 64 regs.
        const int gbase = t * HOP - 512 + n2;
        const float Cs = 0.9807852804f, Ss = 0.1950903220f;   // rot pi/16
        u64 wcc2 = pk2(c0, c0 * Cs - s0 * Ss);
        u64 wss2 = pk2(s0, s0 * Cs + c0 * Ss);
        const u64 CS8  = pk2(0.9238795325f, 0.9238795325f);
        const u64 SS8  = pk2(0.3826834324f, 0.3826834324f);
        const u64 NSS8 = pk2(-0.3826834324f, -0.3826834324f);
        const u64 HALF = pk2(0.5f, 0.5f), NHALF = pk2(-0.5f, -0.5f);
        const u64 NEG1 = pk2(-1.0f, -1.0f);

#pragma unroll
        for (int c2w = 0; c2w < 4; ++c2w) {
            u64 X0p[2], X1p[2], X2p[2];
            if (interior) {
#pragma unroll
                for (int jj = 0; jj < 2; ++jj) {
                    const int off = gbase + 64 * (2 * c2w + jj);
                    X0p[jj] = pk2(__ldg(xb + off),        __ldg(xb + off + 32));
                    X1p[jj] = pk2(__ldg(xb + off + 512),  __ldg(xb + off + 544));
                    X2p[jj] = pk2(__ldg(xb + off + 1024), __ldg(xb + off + 1056));
                }
            } else {
#pragma unroll
                for (int jj = 0; jj < 2; ++jj) {
                    const int off = gbase + 64 * (2 * c2w + jj);
                    X0p[jj] = pk2(__ldg(xb + reflect_idx(off)),
                                  __ldg(xb + reflect_idx(off + 32)));
                    X1p[jj] = pk2(__ldg(xb + reflect_idx(off + 512)),
                                  __ldg(xb + reflect_idx(off + 544)));
                    X2p[jj] = pk2(__ldg(xb + reflect_idx(off + 1024)),
                                  __ldg(xb + reflect_idx(off + 1056)));
                }
            }
#pragma unroll
            for (int jj = 0; jj < 2; ++jj) {
                const int jp = 2 * c2w + jj;
                const int j0 = 2 * jp, j1 = j0 + 1;
                const u64 wm2 = fma2(wcc2, NHALF, HALF);   // 0.5 - 0.5*cos
                const u64 wp2 = fma2(wcc2, HALF, HALF);    // 0.5 + 0.5*cos
                const u64 z0r = mul2(wm2, X0p[jj]);
                const u64 z0i = mul2(wm2, X1p[jj]);
                const u64 z1r = mul2(wp2, X1p[jj]);
                const u64 z1i = mul2(wp2, X2p[jj]);
                if (hA == 0) {                     // uniform branch per warp
                    ar2[jp] = add2(z0r, z1r);
                    ai2[jp] = add2(z0i, z1i);
                } else {
                    const u64 vr = fma2(z1r, NEG1, z0r);
                    const u64 vi = fma2(z1i, NEG1, z0i);
                    const u64 c2_ = pk2(C32[j0], C32[j1]);
                    const u64 s2_ = pk2(S32[j0], S32[j1]);
                    const u64 ns2 = pk2(-S32[j0], -S32[j1]);
                    ar2[jp] = fma2(vi, s2_, mul2(vr, c2_));
                    ai2[jp] = fma2(vr, ns2, mul2(vi, c2_));
                }
                const u64 nc = fma2(wss2, NSS8, mul2(wcc2, CS8));
                wss2 = fma2(wcc2, SS8, mul2(wss2, CS8));
                wcc2 = nc;
            }
        }
        fft16p(ar2, ai2, ar, ai);   // reg r holds A[n2, k1 = 2*brev4(r) + hA]

        // ---- twiddle by W1024^{n2*k1}, k1 = 2m + hA, m = 4q + p (scalar form).
        float w2r, w2i, w4r, w4i, w6r, w6i, w8r, w8i;
        cmul(w2r, w2i, c0, -s0, c0, -s0);          // W^2n2
        cmul(w4r, w4i, w2r, w2i, w2r, w2i);        // W^4n2
        cmul(w6r, w6i, w2r, w2i, w4r, w4i);        // W^6n2
        cmul(w8r, w8i, w4r, w4i, w4r, w4i);        // W^8n2
        const float br = hA ? c0 : 1.0f;
        const float bi = hA ? -s0 : 0.0f;
        float cr[4], ci[4];
        cr[0] = br;  ci[0] = bi;
        cmul(cr[1], ci[1], br, bi, w2r, w2i);
        cmul(cr[2], ci[2], br, bi, w4r, w4i);
        cmul(cr[3], ci[3], br, bi, w6r, w6i);

#pragma unroll
        for (int q = 0; q < 4; ++q) {
#pragma unroll
            for (int p = 0; p < 4; ++p) {
                const int m  = 4 * q + p;
                const int r  = brev4(m);
                const int k1 = 2 * m + hA;
                float vr, vi;
                cmul(vr, vi, ar[r], ai[r], cr[p], ci[p]);
                tile[k1 * TSTRIDE + n2] = make_float2(vr, vi);   // STS.64
                if (q < 3) {
                    float nr, ni;
                    cmul(nr, ni, cr[p], ci[p], w8r, w8i);
                    cr[p] = nr; ci[p] = ni;
                }
            }
        }

        // group barrier: tile stores -> tile loads (2 warps, id grp+1)
        asm volatile("bar.sync %0, %1;" :: "r"(grp + 1), "r"(64) : "memory");

        // ---- stage B: k1 -> lane map keeps k1 and 32-k1 in the SAME warp.
        int k1;
        if (wsub == 0) {
            if (l4 == 0)      k1 = 0;
            else if (l4 == 1) k1 = 16;
            else {
                const int p = l4 >> 1;
                k1 = (l4 & 1) ? (32 - p) : p;
            }
        } else {
            const int p = 8 + (l4 >> 1);
            k1 = (l4 & 1) ? (32 - p) : p;
        }

        // vectorized dual-half reads (LDS.128) + PACKED cross butterfly.
        const float4* t4lo = (const float4*)(tile + k1 * TSTRIDE);       // n2v 0..15
        const float4* t4hi = (const float4*)(tile + k1 * TSTRIDE + 16);  // n2v 16..31
        const u64 NEG1b = pk2(-1.0f, -1.0f);
#pragma unroll
        for (int jq = 0; jq < 8; ++jq) {
            const float4 a0 = t4lo[jq];      // (z[2jq].re, .im, z[2jq+1].re, .im)
            const float4 a1 = t4hi[jq];
            const u64 r0 = pk2(a0.x, a0.z), i0 = pk2(a0.y, a0.w);
            const u64 r1 = pk2(a1.x, a1.z), i1 = pk2(a1.y, a1.w);
            if (hB == 0) {                   // u = a0 + a1
                ar2[jq] = add2(r0, r1);
                ai2[jq] = add2(i0, i1);
            } else {                         // v = (a0 - a1) * W32^j
                const u64 vr = fma2(r1, NEG1b, r0);
                const u64 vi = fma2(i1, NEG1b, i0);
                const int j0 = 2 * jq, j1 = 2 * jq + 1;
                const u64 c2_ = pk2(C32[j0], C32[j1]);
                const u64 s2_ = pk2(S32[j0], S32[j1]);
                const u64 ns2 = pk2(-S32[j0], -S32[j1]);
                ar2[jq] = fma2(vi, s2_, mul2(vr, c2_));
                ai2[jq] = fma2(vr, ns2, mul2(vi, c2_));
            }
        }
        fft16p(ar2, ai2, ar, ai);   // reg r holds Z[k1 + 32*(2*brev4(r) + hB)]

        // group barrier: tile reads done -> magG (union) may be overwritten
        asm volatile("bar.sync %0, %1;" :: "r"(grp + 1), "r"(64) : "memory");

        // ---- conjugate-symmetry unpack + magnitudes.
        const bool k1zero = (wsub == 0) && (l4 == 0);
        const bool k1mid  = (wsub == 0) && (l4 == 1);
        const int msk = k1zero ? 0 : (k1mid ? 16 : 17);
        constexpr int TBL[8] = { 0, 3, 7, 5, 15, 13, 11, 9 };
        float qr_[8], qi_[8];
#pragma unroll
        for (int ri = 0; ri < 8; ++ri) {        // batch all unpack shuffles
            qr_[ri] = __shfl_xor_sync(FULLMASK, ar[15 - 2 * ri], msk);
            qi_[ri] = __shfl_xor_sync(FULLMASK, ai[15 - 2 * ri], msk);
        }
#pragma unroll
        for (int ri = 0; ri < 8; ++ri) {
            const int r = 2 * ri;
            float qr = qr_[ri], qi = qi_[ri];
            if (k1zero && hB == 0) { qr = ar[TBL[ri]]; qi = ai[TBL[ri]]; }
            const float zr = ar[r], zi = ai[r];
            const float e0r = zr + qr, e0i = zi - qi;   // X_t[k]     * 2
            const float e1r = zr - qr, e1i = zi + qi;   // X_{t+1}[k] * 2i
            const float m0 = 0.5f * sqrt_fast(e0r * e0r + e0i * e0i);
            const float m1 = 0.5f * sqrt_fast(e1r * e1r + e1i * e1i);
            const int k2 = 2 * brev4(r) + hB;
            const int k  = k1 + 32 * k2;
            magG[k] = make_float2(m0, m1);              // STS.64 into union
        }
        if (k1zero && hB == 0) {   // k = 512 lives at reg 1 (k2 = 16)
            magG[512] = make_float2(fabsf(ar[1]), fabsf(ai[1]));
        }
    }
    __syncthreads();

    // ---- writeback: thread -> (k, group); predicates only on the last block
    const size_t obase = (size_t)b * CUTOFF * NFRAMES;
    if (blockIdx.x != gridDim.x - 1) {
        for (int i = tid; i < CUTOFF * NGROUP; i += THREADS) {   // 513*4 = 2052
            const int k = i >> 2;
            const int g = i & 3;
            const float2 v = sm2[g * GSTRIDE + k];
            float* orow = out + obase + (size_t)k * NFRAMES + t0 + 2 * g;
            orow[0] = v.x;
            orow[1] = v.y;
        }
    } else {
        for (int i = tid; i < CUTOFF * NGROUP; i += THREADS) {
            const int k = i >> 2;
            const int g = i & 3;
            const float2 v = sm2[g * GSTRIDE + k];
            const int tt = t0 + 2 * g;
            float* orow = out + obase + (size_t)k * NFRAMES;
            if (tt < NFRAMES)     orow[tt] = v.x;
            if (tt + 1 < NFRAMES) orow[tt + 1] = v.y;
        }
    }
}

extern "C" void kernel_launch(void* const* d_in, const int* in_sizes, int n_in,
                              void* d_out, int out_size) {
    const float* x = (const float*)d_in[0];
    // d_in[1] = forward_basis: identical to our windowed DFT; unused.
    float* out = (float*)d_out;

    cudaFuncSetAttribute(stft_kernel,
                         cudaFuncAttributeMaxDynamicSharedMemorySize, SMEM_BYTES);

    dim3 grid((NFRAMES + FPB - 1) / FPB, BATCHES);
    stft_kernel<<<grid, THREADS, SMEM_BYTES>>>(x, out);
}